// round 17
// baseline (speedup 1.0000x reference)
#include <cuda_runtime.h>
#include <cstdint>

#define SEQ    512
#define BATCH  512
#define IN_DIM 128
#define NQ     8
#define D_TOT  136   // IN_DIM + NQ

// Scratch: Zx[s][b][o], o = g*8 + q
__device__ float g_zx[(size_t)SEQ * BATCH * 32];

typedef unsigned long long ull;

// --- packed fp32x2 ops (zx kernel only) ---
__device__ __forceinline__ ull fma2(ull a, ull b, ull c) {
    ull d; asm("fma.rn.f32x2 %0, %1, %2, %3;" : "=l"(d) : "l"(a), "l"(b), "l"(c)); return d;
}
__device__ __forceinline__ ull pack2(float lo, float hi) {
    ull d; asm("mov.b64 %0, {%1, %2};" : "=l"(d) : "r"(__float_as_uint(lo)), "r"(__float_as_uint(hi))); return d;
}
__device__ __forceinline__ void unpack2(ull v, float& lo, float& hi) {
    unsigned a, b; asm("mov.b64 {%0, %1}, %2;" : "=r"(a), "=r"(b) : "l"(v));
    lo = __uint_as_float(a); hi = __uint_as_float(b);
}
__device__ __forceinline__ ull dup2(float x) {
    ull d; unsigned u = __float_as_uint(x);
    asm("mov.b64 %0, {%1, %1};" : "=l"(d) : "r"(u)); return d;
}
// hardware tanh (MUFU.TANH)
__device__ __forceinline__ float tanh_hw(float x) {
    float r; asm("tanh.approx.f32 %0, %1;" : "=f"(r) : "f"(x)); return r;
}

// ============================================================================
// Kernel 1: Zx[row][o] = sum_d x[row][d] * W[o][d] + b[o] + qp[o]
//   128 rows/block -> 256 blocks (>=1.7/SM, 2 warps/SMSP: latency hiding).
//   1 row/thread; d tiled by 16; register double-buffered transposed staging.
// ============================================================================
#define ZX_ROWS 128
#define XPAD    130
#define ZPAD    130
#define NT      (IN_DIM / 16)   // 8 tiles

__global__ __launch_bounds__(128) void zx_kernel(
    const float* __restrict__ x, const float* __restrict__ W,
    const float* __restrict__ b, const float* __restrict__ qp)
{
    __shared__ ulonglong2 Ws[IN_DIM * 4];     // outputs 0..15 of each d (8KB)
    __shared__ ulonglong2 Ws_hi[IN_DIM * 4];  // outputs 16..31 of each d (8KB)
    __shared__ ull bias2[16];
    __shared__ float xs[4352];                // W stage / x tile / z stage

    int tid = threadIdx.x;

    // coalesced W load (4,8,136) = 4352 floats = 1088 float4
    for (int i = tid; i < 1088; i += 128)
        ((float4*)xs)[i] = ((const float4*)W)[i];
    if (tid < 16) bias2[tid] = pack2(b[2 * tid] + qp[2 * tid],
                                     b[2 * tid + 1] + qp[2 * tid + 1]);
    __syncthreads();

    float* WsF   = (float*)Ws;
    float* WsFhi = (float*)Ws_hi;
    for (int i = tid; i < IN_DIM * 32; i += 128) {
        int d = i >> 5, o = i & 31;
        float w = xs[o * D_TOT + d];
        if (o < 16) WsF[d * 16 + o] = w;
        else        WsFhi[d * 16 + (o - 16)] = w;
    }

    int rowbase = blockIdx.x * ZX_ROWS;
    const float* xblk = x + (size_t)rowbase * IN_DIM;

    // staging coords: 512 float4 per tile / 128 threads = 4 each
    int sr = tid >> 2, sdq = tid & 3;         // r base, d-quad

    ull acc[16];
#pragma unroll
    for (int i = 0; i < 16; i++) acc[i] = bias2[i];

    // preload tile 0 into registers
    float4 xreg[4];
#pragma unroll
    for (int it = 0; it < 4; it++) {
        int r = sr + it * 32;
        xreg[it] = *(const float4*)(xblk + (size_t)r * IN_DIM + sdq * 4);
    }

    for (int t = 0; t < NT; t++) {
        __syncthreads();   // xs free (W scatter read at t=0 / prev compute)
        // scatter regs -> transposed xs[d][r]  (bank = 8dq+2j+(tid>>2): CF)
#pragma unroll
        for (int it = 0; it < 4; it++) {
            int r = sr + it * 32;
            float4 v = xreg[it];
            xs[(sdq * 4 + 0) * XPAD + r] = v.x;
            xs[(sdq * 4 + 1) * XPAD + r] = v.y;
            xs[(sdq * 4 + 2) * XPAD + r] = v.z;
            xs[(sdq * 4 + 3) * XPAD + r] = v.w;
        }
        __syncthreads();

        // issue next tile's loads (latency hidden under compute below)
        if (t + 1 < NT) {
#pragma unroll
            for (int it = 0; it < 4; it++) {
                int r = sr + it * 32;
                xreg[it] = *(const float4*)(xblk + (size_t)r * IN_DIM +
                                            (t + 1) * 16 + sdq * 4);
            }
        }

#pragma unroll
        for (int dd = 0; dd < 16; dd++) {
            int d = t * 16 + dd;
            ull xv = dup2(xs[dd * XPAD + tid]);
            const ulonglong2* wlo = Ws    + d * 4;
            const ulonglong2* whi = Ws_hi + d * 4;
#pragma unroll
            for (int j = 0; j < 4; j++) {
                ulonglong2 wp = wlo[j];
                acc[2 * j]     = fma2(xv, wp.x, acc[2 * j]);
                acc[2 * j + 1] = fma2(xv, wp.y, acc[2 * j + 1]);
            }
#pragma unroll
            for (int j = 0; j < 4; j++) {
                ulonglong2 wp = whi[j];
                acc[8 + 2 * j]     = fma2(xv, wp.x, acc[8 + 2 * j]);
                acc[8 + 2 * j + 1] = fma2(xv, wp.y, acc[8 + 2 * j + 1]);
            }
        }
    }

    // output: stage transposed zs[o][r], then coalesced STG.128
    __syncthreads();
#pragma unroll
    for (int j = 0; j < 16; j++) {
        float lo, hi; unpack2(acc[j], lo, hi);
        xs[(2 * j) * ZPAD + tid]     = lo;
        xs[(2 * j + 1) * ZPAD + tid] = hi;
    }
    __syncthreads();
#pragma unroll
    for (int k = 0; k < 8; k++) {
        int idx = k * 128 + tid;
        int r = idx >> 3, d4 = idx & 7;
        float4 v = make_float4(xs[(4 * d4 + 0) * ZPAD + r],
                               xs[(4 * d4 + 1) * ZPAD + r],
                               xs[(4 * d4 + 2) * ZPAD + r],
                               xs[(4 * d4 + 3) * ZPAD + r]);
        *(float4*)(g_zx + (size_t)(rowbase + r) * 32 + d4 * 4) = v;
    }
}

// ============================================================================
// Kernel 2: recurrence. 32 LANES PER BATCH (unchanged from round 16).
// ============================================================================
__global__ void __launch_bounds__(128, 1) rnn_kernel(
    const float* __restrict__ W, const float* __restrict__ h0,
    const float* __restrict__ c0, float* __restrict__ out)
{
    const unsigned FULL = 0xffffffffu;
    int lane = threadIdx.x & 31;
    int warp = threadIdx.x >> 5;
    int q = lane & 7;
    int g = lane >> 3;
    int b = blockIdx.x * 4 + warp;       // batch 0..511

    float Wh[8];
    {
        const float* wr = W + lane * D_TOT + IN_DIM;
#pragma unroll
        for (int j = 0; j < 8; j++) Wh[j] = wr[j];
    }

    float h[8];
#pragma unroll
    for (int j = 0; j < 8; j++) h[j] = h0[b * 8 + j];
    float c = c0[b * 8 + q];

    bool is_g = (g == 2);
    const float ASC = is_g ? 1.0f : 0.5f;
    const float OB  = is_g ? 0.0f : 0.5f;

    bool p1 = (q >= 1), p2 = (q >= 2), p3 = (q >= 3);
    bool p4 = (q >= 4), p5 = (q >= 5), p6 = (q >= 6), p7 = (q >= 7);

    const float* zp = g_zx + ((size_t)b * 32 + lane);
    const int ZSTRIDE = BATCH * 32;

    float zb[4];
#pragma unroll
    for (int u = 0; u < 4; u++) zb[u] = zp[(size_t)u * ZSTRIDE];
    const float* pf = zp + 4 * (size_t)ZSTRIDE;

    float* op = out + ((size_t)b * 8 + q);
    const size_t OSTRIDE = (size_t)BATCH * 8;

    float hq = 0.0f;

    auto step = [&](float zc) {
        float u0 = fmaf(h[0], Wh[0], zc);
        float v0 = h[4] * Wh[4];
#pragma unroll
        for (int j = 1; j < 4; j++) {
            u0 = fmaf(h[j],     Wh[j],     u0);
            v0 = fmaf(h[j + 4], Wh[j + 4], v0);
        }
        float a = __cosf(u0 + v0);

        float c0v = __shfl_sync(FULL, a, 0, 8);
        float c1v = __shfl_sync(FULL, a, 1, 8);
        float c2v = __shfl_sync(FULL, a, 2, 8);
        float c3v = __shfl_sync(FULL, a, 3, 8);
        float c4v = __shfl_sync(FULL, a, 4, 8);
        float c5v = __shfl_sync(FULL, a, 5, 8);
        float c6v = __shfl_sync(FULL, a, 6, 8);
        float c7v = __shfl_sync(FULL, a, 7, 8);
        c1v = p1 ? c1v : 1.0f;
        c2v = p2 ? c2v : 1.0f;
        c3v = p3 ? c3v : 1.0f;
        c4v = p4 ? c4v : 1.0f;
        c5v = p5 ? c5v : 1.0f;
        c6v = p6 ? c6v : 1.0f;
        c7v = p7 ? c7v : 1.0f;
        float m01 = c0v * c1v, m23 = c2v * c3v;
        float m45 = c4v * c5v, m67 = c6v * c7v;
        float prod = (m01 * m23) * (m45 * m67);

        float V = fmaf(ASC, tanh_hw(ASC * prod), OB);

        float fv = __shfl_sync(FULL, V, q);
        float iv = __shfl_sync(FULL, V, 8 + q);
        float gv = __shfl_sync(FULL, V, 16 + q);
        float ov = __shfl_sync(FULL, V, 24 + q);

        c = fmaf(fv, c, iv * gv);
        hq = ov * tanh_hw(c);

#pragma unroll
        for (int j = 0; j < 8; j++)
            h[j] = __shfl_sync(FULL, hq, j, 8);

        *op = hq;
        op += OSTRIDE;
    };

    for (int s = 0; s <= SEQ - 8; s += 4) {
#pragma unroll
        for (int u = 0; u < 4; u++) {
            float zn = *pf; pf += ZSTRIDE;
            step(zb[u]);
            zb[u] = zn;
        }
    }
#pragma unroll
    for (int u = 0; u < 4; u++)
        step(zb[u]);

    size_t base = (size_t)SEQ * BATCH * 8;
    out[base + (size_t)b * 8 + q]             = hq;
    out[base + BATCH * 8 + (size_t)b * 8 + q] = c;
}

extern "C" void kernel_launch(void* const* d_in, const int* in_sizes, int n_in,
                              void* d_out, int out_size) {
    const float* x  = (const float*)d_in[0];   // inputs (512,512,128)
    const float* h0 = (const float*)d_in[1];   // (512,8)
    const float* c0 = (const float*)d_in[2];   // (512,8)
    const float* W  = (const float*)d_in[3];   // (4,8,136)
    const float* b  = (const float*)d_in[4];   // (4,8)
    const float* qp = (const float*)d_in[5];   // (4,8)
    float* out = (float*)d_out;

    zx_kernel<<<(SEQ * BATCH) / ZX_ROWS, 128>>>(x, W, b, qp);
    rnn_kernel<<<BATCH / 4, 128>>>(W, h0, c0, out);
}